// round 12
// baseline (speedup 1.0000x reference)
#include <cuda_runtime.h>
#include <cuda_bf16.h>
#include <math.h>
#include <stdint.h>

#define NN 50000
#define EE 800000
#define DD 128
#define HH 8
#define CNT_PAD 53248   // 1024 threads * 52 ints

// ---------------- scratch (static device arrays, no allocation) -------------
__device__ float g_Q[NN * DD];
__device__ float g_K[NN * DD];
__device__ float g_V[NN * DD];
__device__ float g_h[NN * DD];
// bf16 hi/lo splits of activations, packed bf16x2 (pair p = cols 2p, 2p+1)
__device__ unsigned int g_xhi[NN * 64];
__device__ unsigned int g_xlo[NN * 64];
__device__ unsigned int g_thi[NN * 64];
__device__ unsigned int g_tlo[NN * 64];
// W pre-baked into m16n8k16 B-fragment layout: [matrix][(kk*16+nn)*32 + lane]
__device__ uint2 g_wfh[4][4096];
__device__ uint2 g_wfl[4][4096];
// CSR by destination
__device__ __align__(16) int g_cnt[CNT_PAD];
__device__ int g_rowptr[NN + 1];
__device__ int g_off[NN];
__device__ int g_esrc[EE];

// ---------------- helpers ---------------------------------------------------
__device__ __forceinline__ unsigned int smem_u32(const void* p) {
    unsigned int a;
    asm("{ .reg .u64 t; cvta.to.shared.u64 t, %1; cvt.u32.u64 %0, t; }" : "=r"(a) : "l"(p));
    return a;
}

__device__ __forceinline__ unsigned int pack_bf(float a, float b) {
    __nv_bfloat162 t = __floats2bfloat162_rn(a, b);
    return *reinterpret_cast<unsigned int*>(&t);
}

#define MMA_BF16(c, a, b0v, b1v)                                               \
    asm volatile("mma.sync.aligned.m16n8k16.row.col.f32.bf16.bf16.f32 "        \
                 "{%0,%1,%2,%3}, {%4,%5,%6,%7}, {%8,%9}, {%0,%1,%2,%3};"       \
                 : "+f"((c)[0]), "+f"((c)[1]), "+f"((c)[2]), "+f"((c)[3])      \
                 : "r"((a)[0]), "r"((a)[1]), "r"((a)[2]), "r"((a)[3]),         \
                   "r"(b0v), "r"(b1v))

#define LDMATRIX_X4(r, addr)                                                   \
    asm volatile("ldmatrix.sync.aligned.m8n8.x4.shared.b16 {%0,%1,%2,%3}, [%4];" \
                 : "=r"((r)[0]), "=r"((r)[1]), "=r"((r)[2]), "=r"((r)[3])      \
                 : "r"(addr))

// ---------------------------------------------------------------------------
// Convert x -> bf16 hi/lo pairs; also zero the CSR histogram counters.
// ---------------------------------------------------------------------------
__global__ void convert_x(const float* __restrict__ x) {
    int i = blockIdx.x * 256 + threadIdx.x;
    if (i < CNT_PAD) g_cnt[i] = 0;
    if (i >= NN * 64) return;
    float2 v = reinterpret_cast<const float2*>(x)[i];
    __nv_bfloat162 hp = __floats2bfloat162_rn(v.x, v.y);
    float l0 = v.x - __bfloat162float(hp.x);
    float l1 = v.y - __bfloat162float(hp.y);
    g_xhi[i] = *reinterpret_cast<unsigned int*>(&hp);
    g_xlo[i] = pack_bf(l0, l1);
}

// ---------------------------------------------------------------------------
// CSR build: histogram (x4 vectorized) -> single-block scan (int4) -> scatter
// ---------------------------------------------------------------------------
__global__ void hist_kernel(const int* __restrict__ dst) {
    int i = blockIdx.x * 256 + threadIdx.x;
    if (i < EE / 4) {
        int4 d = reinterpret_cast<const int4*>(dst)[i];
        atomicAdd(&g_cnt[d.x], 1);
        atomicAdd(&g_cnt[d.y], 1);
        atomicAdd(&g_cnt[d.z], 1);
        atomicAdd(&g_cnt[d.w], 1);
    }
}

__global__ void scan_kernel() {
    __shared__ int ssum[1024];
    const int CH4 = 13;               // 13 int4 = 52 ints per thread
    int t = threadIdx.x;
    int base4 = t * CH4;

    int4 vals[CH4];
    int local = 0;
#pragma unroll
    for (int i = 0; i < CH4; i++) {
        vals[i] = reinterpret_cast<const int4*>(g_cnt)[base4 + i];
        local += vals[i].x + vals[i].y + vals[i].z + vals[i].w;
    }
    ssum[t] = local;
    __syncthreads();
    for (int o = 1; o < 1024; o <<= 1) {
        int u = (t >= o) ? ssum[t - o] : 0;
        __syncthreads();
        ssum[t] += u;
        __syncthreads();
    }
    int run = ssum[t] - local;        // exclusive prefix
    int base = t * 52;
#pragma unroll
    for (int i = 0; i < CH4; i++) {
        int idx = base + i * 4;
        int4 v = vals[i];
        if (idx     < NN) { g_rowptr[idx]     = run; g_off[idx]     = run; } run += v.x;
        if (idx + 1 < NN) { g_rowptr[idx + 1] = run; g_off[idx + 1] = run; } run += v.y;
        if (idx + 2 < NN) { g_rowptr[idx + 2] = run; g_off[idx + 2] = run; } run += v.z;
        if (idx + 3 < NN) { g_rowptr[idx + 3] = run; g_off[idx + 3] = run; } run += v.w;
    }
    if (t == 1023) g_rowptr[NN] = run;
}

__global__ void scatter_kernel(const int* __restrict__ src, const int* __restrict__ dst) {
    int i = blockIdx.x * 256 + threadIdx.x;
    if (i < EE / 4) {
        int4 d = reinterpret_cast<const int4*>(dst)[i];
        int4 s = reinterpret_cast<const int4*>(src)[i];
        int p0 = atomicAdd(&g_off[d.x], 1); g_esrc[p0] = s.x;
        int p1 = atomicAdd(&g_off[d.y], 1); g_esrc[p1] = s.y;
        int p2 = atomicAdd(&g_off[d.z], 1); g_esrc[p2] = s.z;
        int p3 = atomicAdd(&g_off[d.w], 1); g_esrc[p3] = s.w;
    }
}

// ---------------------------------------------------------------------------
// Bake W (4 matrices) into mma.sync B-fragment layout (hi + lo splits).
// ---------------------------------------------------------------------------
__global__ void convert_w(const float* __restrict__ Wq, const float* __restrict__ Wk,
                          const float* __restrict__ Wv, const float* __restrict__ Wo) {
    int m = blockIdx.y;
    const float* W = (m == 0) ? Wq : (m == 1) ? Wk : (m == 2) ? Wv : Wo;
    int i = blockIdx.x * 256 + threadIdx.x;
    if (i >= 4096) return;
    int lane = i & 31, nn = (i >> 5) & 15, kk = i >> 9;
    int g = lane >> 2, tig = lane & 3;
    int k0 = kk * 16 + 2 * tig;
    int col = nn * 8 + g;

    float w00 = W[(k0)     * 128 + col];
    float w01 = W[(k0 + 1) * 128 + col];
    float w10 = W[(k0 + 8) * 128 + col];
    float w11 = W[(k0 + 9) * 128 + col];

    __nv_bfloat16 h00 = __float2bfloat16_rn(w00);
    __nv_bfloat16 h01 = __float2bfloat16_rn(w01);
    __nv_bfloat16 h10 = __float2bfloat16_rn(w10);
    __nv_bfloat16 h11 = __float2bfloat16_rn(w11);

    g_wfh[m][i] = make_uint2(pack_bf(w00, w01), pack_bf(w10, w11));
    g_wfl[m][i] = make_uint2(
        pack_bf(w00 - __bfloat162float(h00), w01 - __bfloat162float(h01)),
        pack_bf(w10 - __bfloat162float(h10), w11 - __bfloat162float(h11)));
}

// ---------------------------------------------------------------------------
// mma.sync GEMM: D[128 rows, 128 cols] = A @ W, bf16x3 split, fp32 accum.
// (unchanged — term-major distance-4 chains + rolling prefetch)
// ---------------------------------------------------------------------------
__global__ void __launch_bounds__(256, 3)
mma_gemm(int a_is_t, int w_base, const float* __restrict__ b0,
         const float* __restrict__ b1, const float* __restrict__ b2,
         float* __restrict__ dout, int is_out) {
    extern __shared__ char smem[];
    const int A_STRIDE_B = 272;
    const int OFF_LO = 128 * A_STRIDE_B;
    int t = threadIdx.x, warp = t >> 5, lane = t & 31;
    int sel = blockIdx.y;
    int row0 = blockIdx.x * 128;

    const unsigned int* __restrict__ Ahi = a_is_t ? g_thi : g_xhi;
    const unsigned int* __restrict__ Alo = a_is_t ? g_tlo : g_xlo;
    const uint2* __restrict__ wfh = g_wfh[w_base + sel];
    const uint2* __restrict__ wfl = g_wfl[w_base + sel];
    const float* bias = is_out ? b0 : (sel == 0 ? b0 : sel == 1 ? b1 : b2);
    float* outp = is_out ? dout : (sel == 0 ? g_Q : sel == 1 ? g_K : g_V);

    for (int i = t; i < 8192; i += 256) {
        int row = i >> 6, p = i & 63;
        int grow = row0 + row;
        unsigned int vh = 0, vl = 0;
        if (grow < NN) { vh = Ahi[grow * 64 + p]; vl = Alo[grow * 64 + p]; }
        int off = row * A_STRIDE_B + p * 4;
        *reinterpret_cast<unsigned int*>(smem + off)          = vh;
        *reinterpret_cast<unsigned int*>(smem + OFF_LO + off) = vl;
    }
    __syncthreads();

    int rowsel = (lane & 7) | (((lane >> 3) & 1) << 3);
    int colblk = lane >> 4;
    unsigned int sb = smem_u32(smem);
    unsigned int a_addr = sb + (warp * 16 + rowsel) * A_STRIDE_B + colblk * 16;

    int g = lane >> 2, tig = lane & 3;
    int r_lo = row0 + warp * 16 + g;
    int r_hi = r_lo + 8;

#pragma unroll 1
    for (int half = 0; half < 2; half++) {
        const uint2* bh_base = wfh + half * 8 * 32 + lane;
        const uint2* bl_base = wfl + half * 8 * 32 + lane;

        float acc[8][4];
#pragma unroll
        for (int nn = 0; nn < 8; nn++)
#pragma unroll
            for (int c = 0; c < 4; c++) acc[nn][c] = 0.f;

        uint2 bhA[4], blA[4];
#pragma unroll
        for (int i = 0; i < 4; i++) {
            bhA[i] = __ldg(bh_base + i * 32);
            blA[i] = __ldg(bl_base + i * 32);
        }

#pragma unroll 1
        for (int kk = 0; kk < 8; kk++) {
            unsigned int a_hi[4], a_lo[4];
            LDMATRIX_X4(a_hi, a_addr + kk * 32);
            LDMATRIX_X4(a_lo, a_addr + OFF_LO + kk * 32);

            uint2 bhB[4], blB[4];
#pragma unroll
            for (int i = 0; i < 4; i++) {
                bhB[i] = __ldg(bh_base + (kk * 16 + 4 + i) * 32);
                blB[i] = __ldg(bl_base + (kk * 16 + 4 + i) * 32);
            }

#pragma unroll
            for (int i = 0; i < 4; i++) MMA_BF16(acc[i], a_hi, bhA[i].x, bhA[i].y);
#pragma unroll
            for (int i = 0; i < 4; i++) MMA_BF16(acc[i], a_hi, blA[i].x, blA[i].y);
#pragma unroll
            for (int i = 0; i < 4; i++) MMA_BF16(acc[i], a_lo, bhA[i].x, bhA[i].y);

            if (kk < 7) {
#pragma unroll
                for (int i = 0; i < 4; i++) {
                    bhA[i] = __ldg(bh_base + ((kk + 1) * 16 + i) * 32);
                    blA[i] = __ldg(bl_base + ((kk + 1) * 16 + i) * 32);
                }
            }

#pragma unroll
            for (int i = 0; i < 4; i++) MMA_BF16(acc[4 + i], a_hi, bhB[i].x, bhB[i].y);
#pragma unroll
            for (int i = 0; i < 4; i++) MMA_BF16(acc[4 + i], a_hi, blB[i].x, blB[i].y);
#pragma unroll
            for (int i = 0; i < 4; i++) MMA_BF16(acc[4 + i], a_lo, bhB[i].x, bhB[i].y);
        }

#pragma unroll
        for (int nn = 0; nn < 8; nn++) {
            int col = (half * 8 + nn) * 8 + 2 * tig;
            float2 bb = *reinterpret_cast<const float2*>(bias + col);
            if (r_lo < NN) {
                float2 o;
                if (is_out) {
                    float2 hv = *reinterpret_cast<const float2*>(g_h + (size_t)r_lo * DD + col);
                    o.x = hv.x + fmaxf(acc[nn][0] + bb.x, 0.f);
                    o.y = hv.y + fmaxf(acc[nn][1] + bb.y, 0.f);
                } else {
                    o.x = acc[nn][0] + bb.x;
                    o.y = acc[nn][1] + bb.y;
                }
                *reinterpret_cast<float2*>(outp + (size_t)r_lo * DD + col) = o;
            }
            if (r_hi < NN) {
                float2 o;
                if (is_out) {
                    float2 hv = *reinterpret_cast<const float2*>(g_h + (size_t)r_hi * DD + col);
                    o.x = hv.x + fmaxf(acc[nn][2] + bb.x, 0.f);
                    o.y = hv.y + fmaxf(acc[nn][3] + bb.y, 0.f);
                } else {
                    o.x = acc[nn][2] + bb.x;
                    o.y = acc[nn][3] + bb.y;
                }
                *reinterpret_cast<float2*>(outp + (size_t)r_hi * DD + col) = o;
            }
        }
    }
}

// ---------------------------------------------------------------------------
// Fused edge + norm kernel: one warp per destination node, unroll-4 over
// edges (8 gathers in flight). Register accumulation, no atomics. Then
// normalize + residual + LN1 -> g_h + LN2 -> bf16 split.
// ---------------------------------------------------------------------------
__global__ void __launch_bounds__(256)
edge_norm_kernel(const float* __restrict__ x,
                 const float* __restrict__ gamma1, const float* __restrict__ beta1,
                 const float* __restrict__ gamma2, const float* __restrict__ beta2) {
    int node = (blockIdx.x * blockDim.x + threadIdx.x) >> 5;
    int lane = threadIdx.x & 31;
    if (node >= NN) return;

    float4 qv = reinterpret_cast<const float4*>(g_Q + (size_t)node * DD)[lane];
    int beg = g_rowptr[node];
    int end = g_rowptr[node + 1];

    float4 wacc = make_float4(0.f, 0.f, 0.f, 0.f);
    float zacc = 0.f;

    int i = beg;
    for (; i + 4 <= end; i += 4) {
        int s0 = __ldg(g_esrc + i);
        int s1 = __ldg(g_esrc + i + 1);
        int s2 = __ldg(g_esrc + i + 2);
        int s3 = __ldg(g_esrc + i + 3);
        // issue all 8 row gathers before consuming anything
        float4 kv0 = reinterpret_cast<const float4*>(g_K + (size_t)s0 * DD)[lane];
        float4 kv1 = reinterpret_cast<const float4*>(g_K + (size_t)s1 * DD)[lane];
        float4 kv2 = reinterpret_cast<const float4*>(g_K + (size_t)s2 * DD)[lane];
        float4 kv3 = reinterpret_cast<const float4*>(g_K + (size_t)s3 * DD)[lane];
        float4 vv0 = reinterpret_cast<const float4*>(g_V + (size_t)s0 * DD)[lane];
        float4 vv1 = reinterpret_cast<const float4*>(g_V + (size_t)s1 * DD)[lane];
        float4 vv2 = reinterpret_cast<const float4*>(g_V + (size_t)s2 * DD)[lane];
        float4 vv3 = reinterpret_cast<const float4*>(g_V + (size_t)s3 * DD)[lane];

        float p0 = kv0.x * qv.x + kv0.y * qv.y + kv0.z * qv.z + kv0.w * qv.w;
        float p1 = kv1.x * qv.x + kv1.y * qv.y + kv1.z * qv.z + kv1.w * qv.w;
        float p2 = kv2.x * qv.x + kv2.y * qv.y + kv2.z * qv.z + kv2.w * qv.w;
        float p3 = kv3.x * qv.x + kv3.y * qv.y + kv3.z * qv.z + kv3.w * qv.w;
        p0 += __shfl_xor_sync(0xffffffffu, p0, 1);
        p1 += __shfl_xor_sync(0xffffffffu, p1, 1);
        p2 += __shfl_xor_sync(0xffffffffu, p2, 1);
        p3 += __shfl_xor_sync(0xffffffffu, p3, 1);
        p0 += __shfl_xor_sync(0xffffffffu, p0, 2);
        p1 += __shfl_xor_sync(0xffffffffu, p1, 2);
        p2 += __shfl_xor_sync(0xffffffffu, p2, 2);
        p3 += __shfl_xor_sync(0xffffffffu, p3, 2);

        float sc0 = __expf(fminf(fmaxf(p0 * 0.25f, -5.f), 5.f));
        float sc1 = __expf(fminf(fmaxf(p1 * 0.25f, -5.f), 5.f));
        float sc2 = __expf(fminf(fmaxf(p2 * 0.25f, -5.f), 5.f));
        float sc3 = __expf(fminf(fmaxf(p3 * 0.25f, -5.f), 5.f));

        wacc.x += vv0.x * sc0 + vv1.x * sc1 + vv2.x * sc2 + vv3.x * sc3;
        wacc.y += vv0.y * sc0 + vv1.y * sc1 + vv2.y * sc2 + vv3.y * sc3;
        wacc.z += vv0.z * sc0 + vv1.z * sc1 + vv2.z * sc2 + vv3.z * sc3;
        wacc.w += vv0.w * sc0 + vv1.w * sc1 + vv2.w * sc2 + vv3.w * sc3;
        zacc += sc0 + sc1 + sc2 + sc3;
    }
    for (; i < end; i++) {
        int s = __ldg(g_esrc + i);
        float4 kv = reinterpret_cast<const float4*>(g_K + (size_t)s * DD)[lane];
        float4 vv = reinterpret_cast<const float4*>(g_V + (size_t)s * DD)[lane];
        float p = kv.x * qv.x + kv.y * qv.y + kv.z * qv.z + kv.w * qv.w;
        p += __shfl_xor_sync(0xffffffffu, p, 1);
        p += __shfl_xor_sync(0xffffffffu, p, 2);
        float sc = __expf(fminf(fmaxf(p * 0.25f, -5.f), 5.f));
        wacc.x += vv.x * sc; wacc.y += vv.y * sc;
        wacc.z += vv.z * sc; wacc.w += vv.w * sc;
        zacc += sc;
    }

    float rz = 1.f / (zacc + 1e-3f);
    float4 xv = reinterpret_cast<const float4*>(x + (size_t)node * DD)[lane];

    float4 y;
    y.x = xv.x + wacc.x * rz;
    y.y = xv.y + wacc.y * rz;
    y.z = xv.z + wacc.z * rz;
    y.w = xv.w + wacc.w * rz;

    // --- LN1 ---
    float s  = y.x + y.y + y.z + y.w;
    float sq = y.x * y.x + y.y * y.y + y.z * y.z + y.w * y.w;
#pragma unroll
    for (int o = 16; o > 0; o >>= 1) {
        s  += __shfl_xor_sync(0xffffffffu, s,  o);
        sq += __shfl_xor_sync(0xffffffffu, sq, o);
    }
    float mu  = s * (1.f / DD);
    float var = sq * (1.f / DD) - mu * mu;
    float inv = rsqrtf(var + 1e-5f);

    float4 g1 = reinterpret_cast<const float4*>(gamma1)[lane];
    float4 b1 = reinterpret_cast<const float4*>(beta1)[lane];
    float4 h;
    h.x = (y.x - mu) * inv * g1.x + b1.x;
    h.y = (y.y - mu) * inv * g1.y + b1.y;
    h.z = (y.z - mu) * inv * g1.z + b1.z;
    h.w = (y.w - mu) * inv * g1.w + b1.w;
    reinterpret_cast<float4*>(g_h + (size_t)node * DD)[lane] = h;

    // --- LN2 ---
    float s2  = h.x + h.y + h.z + h.w;
    float sq2 = h.x * h.x + h.y * h.y + h.z * h.z + h.w * h.w;
#pragma unroll
    for (int o = 16; o > 0; o >>= 1) {
        s2  += __shfl_xor_sync(0xffffffffu, s2,  o);
        sq2 += __shfl_xor_sync(0xffffffffu, sq2, o);
    }
    float mu2  = s2 * (1.f / DD);
    float var2 = sq2 * (1.f / DD) - mu2 * mu2;
    float inv2 = rsqrtf(var2 + 1e-5f);

    float4 g2 = reinterpret_cast<const float4*>(gamma2)[lane];
    float4 b2 = reinterpret_cast<const float4*>(beta2)[lane];
    float4 tt;
    tt.x = (h.x - mu2) * inv2 * g2.x + b2.x;
    tt.y = (h.y - mu2) * inv2 * g2.y + b2.y;
    tt.z = (h.z - mu2) * inv2 * g2.z + b2.z;
    tt.w = (h.w - mu2) * inv2 * g2.w + b2.w;

    __nv_bfloat162 h01 = __floats2bfloat162_rn(tt.x, tt.y);
    __nv_bfloat162 h23 = __floats2bfloat162_rn(tt.z, tt.w);
    float l0 = tt.x - __bfloat162float(h01.x);
    float l1 = tt.y - __bfloat162float(h01.y);
    float l2 = tt.z - __bfloat162float(h23.x);
    float l3 = tt.w - __bfloat162float(h23.y);
    int base = node * 64 + lane * 2;
    g_thi[base]     = *reinterpret_cast<unsigned int*>(&h01);
    g_thi[base + 1] = *reinterpret_cast<unsigned int*>(&h23);
    g_tlo[base]     = pack_bf(l0, l1);
    g_tlo[base + 1] = pack_bf(l2, l3);
}

// ---------------------------------------------------------------------------
extern "C" void kernel_launch(void* const* d_in, const int* in_sizes, int n_in,
                              void* d_out, int out_size) {
    const float* x      = (const float*)d_in[0];
    const int*   src    = (const int*)  d_in[1];
    const int*   dst    = (const int*)  d_in[2];
    const float* Wq     = (const float*)d_in[3];
    const float* bq     = (const float*)d_in[4];
    const float* Wk     = (const float*)d_in[5];
    const float* bk     = (const float*)d_in[6];
    const float* Wv     = (const float*)d_in[7];
    const float* bv     = (const float*)d_in[8];
    const float* Wo     = (const float*)d_in[9];
    const float* bo     = (const float*)d_in[10];
    const float* gamma1 = (const float*)d_in[11];
    const float* beta1  = (const float*)d_in[12];
    const float* gamma2 = (const float*)d_in[13];
    const float* beta2  = (const float*)d_in[14];
    float* out = (float*)d_out;

    const int MMA_SMEM = 2 * 128 * 272;  // 69632 B
    cudaFuncSetAttribute(mma_gemm, cudaFuncAttributeMaxDynamicSharedMemorySize, MMA_SMEM);

    // x split + zero histogram counters
    convert_x<<<(NN * 64 + 255) / 256, 256>>>(x);

    // CSR build
    hist_kernel<<<(EE / 4 + 255) / 256, 256>>>(dst);
    scan_kernel<<<1, 1024>>>();
    scatter_kernel<<<(EE / 4 + 255) / 256, 256>>>(src, dst);

    // W fragment bake
    convert_w<<<dim3(16, 4), 256>>>(Wq, Wk, Wv, Wo);

    // QKV projections (mma.sync bf16x3)
    dim3 qkv_grid((NN + 127) / 128, 3);
    mma_gemm<<<qkv_grid, 256, MMA_SMEM>>>(0, 0, bq, bk, bv, nullptr, 0);

    // fused edge scores + scatter + normalize + LN1 + LN2(+split)
    edge_norm_kernel<<<(NN + 7) / 8, 256>>>(x, gamma1, beta1, gamma2, beta2);

    // output projection + relu + residual
    mma_gemm<<<dim3((NN + 127) / 128, 1), 256, MMA_SMEM>>>(1, 3, bo, bo, bo, out, 1);
}

// round 13
// speedup vs baseline: 1.5828x; 1.5828x over previous
#include <cuda_runtime.h>
#include <cuda_bf16.h>
#include <cuda_fp16.h>
#include <math.h>
#include <stdint.h>

#define NN 50000
#define EE 800000
#define DD 128
#define HH 8

// ---------------- scratch (static device arrays, no allocation) -------------
// Q/K/V stored as fp16 (half2-packed): row = 64 uints = 128 halves
__device__ unsigned int g_Qh[NN * 64];
__device__ unsigned int g_Kh[NN * 64];
__device__ unsigned int g_Vh[NN * 64];
__device__ float g_wV[NN * DD];
__device__ float g_z[NN * HH];
__device__ float g_h[NN * DD];
// bf16 hi/lo splits of activations, packed bf16x2 (pair p = cols 2p, 2p+1)
__device__ unsigned int g_xhi[NN * 64];
__device__ unsigned int g_xlo[NN * 64];
__device__ unsigned int g_thi[NN * 64];
__device__ unsigned int g_tlo[NN * 64];
// W pre-baked into m16n8k16 B-fragment layout: [matrix][(kk*16+nn)*32 + lane]
__device__ uint2 g_wfh[4][4096];
__device__ uint2 g_wfl[4][4096];

// ---------------- helpers ---------------------------------------------------
__device__ __forceinline__ unsigned int smem_u32(const void* p) {
    unsigned int a;
    asm("{ .reg .u64 t; cvta.to.shared.u64 t, %1; cvt.u32.u64 %0, t; }" : "=r"(a) : "l"(p));
    return a;
}

__device__ __forceinline__ unsigned int pack_bf(float a, float b) {
    __nv_bfloat162 t = __floats2bfloat162_rn(a, b);
    return *reinterpret_cast<unsigned int*>(&t);
}

__device__ __forceinline__ unsigned int pack_h2(float a, float b) {
    __half2 t = __floats2half2_rn(a, b);
    return *reinterpret_cast<unsigned int*>(&t);
}

__device__ __forceinline__ float2 unpack_h2(unsigned int u) {
    return __half22float2(*reinterpret_cast<__half2*>(&u));
}

#define MMA_BF16(c, a, b0v, b1v)                                               \
    asm volatile("mma.sync.aligned.m16n8k16.row.col.f32.bf16.bf16.f32 "        \
                 "{%0,%1,%2,%3}, {%4,%5,%6,%7}, {%8,%9}, {%0,%1,%2,%3};"       \
                 : "+f"((c)[0]), "+f"((c)[1]), "+f"((c)[2]), "+f"((c)[3])      \
                 : "r"((a)[0]), "r"((a)[1]), "r"((a)[2]), "r"((a)[3]),         \
                   "r"(b0v), "r"(b1v))

#define LDMATRIX_X4(r, addr)                                                   \
    asm volatile("ldmatrix.sync.aligned.m8n8.x4.shared.b16 {%0,%1,%2,%3}, [%4];" \
                 : "=r"((r)[0]), "=r"((r)[1]), "=r"((r)[2]), "=r"((r)[3])      \
                 : "r"(addr))

// ---------------------------------------------------------------------------
// Zero accumulators
// ---------------------------------------------------------------------------
__global__ void zero_kernel() {
    int idx = blockIdx.x * 256 + threadIdx.x;
    float4 zf = make_float4(0.f, 0.f, 0.f, 0.f);
    if (idx < NN * DD / 4) reinterpret_cast<float4*>(g_wV)[idx] = zf;
    if (idx < NN * HH)     g_z[idx] = 0.f;
}

// ---------------------------------------------------------------------------
// Convert x -> bf16 hi/lo pairs
// ---------------------------------------------------------------------------
__global__ void convert_x(const float* __restrict__ x) {
    int i = blockIdx.x * 256 + threadIdx.x;
    if (i >= NN * 64) return;
    float2 v = reinterpret_cast<const float2*>(x)[i];
    __nv_bfloat162 hp = __floats2bfloat162_rn(v.x, v.y);
    float l0 = v.x - __bfloat162float(hp.x);
    float l1 = v.y - __bfloat162float(hp.y);
    g_xhi[i] = *reinterpret_cast<unsigned int*>(&hp);
    g_xlo[i] = pack_bf(l0, l1);
}

// ---------------------------------------------------------------------------
// Bake W (4 matrices) into mma.sync B-fragment layout (hi + lo splits).
// ---------------------------------------------------------------------------
__global__ void convert_w(const float* __restrict__ Wq, const float* __restrict__ Wk,
                          const float* __restrict__ Wv, const float* __restrict__ Wo) {
    int m = blockIdx.y;
    const float* W = (m == 0) ? Wq : (m == 1) ? Wk : (m == 2) ? Wv : Wo;
    int i = blockIdx.x * 256 + threadIdx.x;
    if (i >= 4096) return;
    int lane = i & 31, nn = (i >> 5) & 15, kk = i >> 9;
    int g = lane >> 2, tig = lane & 3;
    int k0 = kk * 16 + 2 * tig;
    int col = nn * 8 + g;

    float w00 = W[(k0)     * 128 + col];
    float w01 = W[(k0 + 1) * 128 + col];
    float w10 = W[(k0 + 8) * 128 + col];
    float w11 = W[(k0 + 9) * 128 + col];

    __nv_bfloat16 h00 = __float2bfloat16_rn(w00);
    __nv_bfloat16 h01 = __float2bfloat16_rn(w01);
    __nv_bfloat16 h10 = __float2bfloat16_rn(w10);
    __nv_bfloat16 h11 = __float2bfloat16_rn(w11);

    g_wfh[m][i] = make_uint2(pack_bf(w00, w01), pack_bf(w10, w11));
    g_wfl[m][i] = make_uint2(
        pack_bf(w00 - __bfloat162float(h00), w01 - __bfloat162float(h01)),
        pack_bf(w10 - __bfloat162float(h10), w11 - __bfloat162float(h11)));
}

// ---------------------------------------------------------------------------
// mma.sync GEMM: D[128 rows, 128 cols] = A @ W, bf16x3 split, fp32 accum.
// Term-major distance-4 chains + rolling B prefetch (proven R10 mainloop).
// qkv mode (is_out=0): epilogue packs D+bias to fp16 half2 -> g_Qh/g_Kh/g_Vh
// out mode (is_out=1): out = g_h + relu(D + bo) fp32
// ---------------------------------------------------------------------------
__global__ void __launch_bounds__(256, 3)
mma_gemm(int a_is_t, int w_base, const float* __restrict__ b0,
         const float* __restrict__ b1, const float* __restrict__ b2,
         float* __restrict__ dout, int is_out) {
    extern __shared__ char smem[];
    const int A_STRIDE_B = 272;
    const int OFF_LO = 128 * A_STRIDE_B;
    int t = threadIdx.x, warp = t >> 5, lane = t & 31;
    int sel = blockIdx.y;
    int row0 = blockIdx.x * 128;

    const unsigned int* __restrict__ Ahi = a_is_t ? g_thi : g_xhi;
    const unsigned int* __restrict__ Alo = a_is_t ? g_tlo : g_xlo;
    const uint2* __restrict__ wfh = g_wfh[w_base + sel];
    const uint2* __restrict__ wfl = g_wfl[w_base + sel];
    const float* bias = is_out ? b0 : (sel == 0 ? b0 : sel == 1 ? b1 : b2);
    unsigned int* oph = (sel == 0) ? g_Qh : (sel == 1) ? g_Kh : g_Vh;

    for (int i = t; i < 8192; i += 256) {
        int row = i >> 6, p = i & 63;
        int grow = row0 + row;
        unsigned int vh = 0, vl = 0;
        if (grow < NN) { vh = Ahi[grow * 64 + p]; vl = Alo[grow * 64 + p]; }
        int off = row * A_STRIDE_B + p * 4;
        *reinterpret_cast<unsigned int*>(smem + off)          = vh;
        *reinterpret_cast<unsigned int*>(smem + OFF_LO + off) = vl;
    }
    __syncthreads();

    int rowsel = (lane & 7) | (((lane >> 3) & 1) << 3);
    int colblk = lane >> 4;
    unsigned int sb = smem_u32(smem);
    unsigned int a_addr = sb + (warp * 16 + rowsel) * A_STRIDE_B + colblk * 16;

    int g = lane >> 2, tig = lane & 3;
    int r_lo = row0 + warp * 16 + g;
    int r_hi = r_lo + 8;

#pragma unroll 1
    for (int half = 0; half < 2; half++) {
        const uint2* bh_base = wfh + half * 8 * 32 + lane;
        const uint2* bl_base = wfl + half * 8 * 32 + lane;

        float acc[8][4];
#pragma unroll
        for (int nn = 0; nn < 8; nn++)
#pragma unroll
            for (int c = 0; c < 4; c++) acc[nn][c] = 0.f;

        uint2 bhA[4], blA[4];
#pragma unroll
        for (int i = 0; i < 4; i++) {
            bhA[i] = __ldg(bh_base + i * 32);
            blA[i] = __ldg(bl_base + i * 32);
        }

#pragma unroll 1
        for (int kk = 0; kk < 8; kk++) {
            unsigned int a_hi[4], a_lo[4];
            LDMATRIX_X4(a_hi, a_addr + kk * 32);
            LDMATRIX_X4(a_lo, a_addr + OFF_LO + kk * 32);

            uint2 bhB[4], blB[4];
#pragma unroll
            for (int i = 0; i < 4; i++) {
                bhB[i] = __ldg(bh_base + (kk * 16 + 4 + i) * 32);
                blB[i] = __ldg(bl_base + (kk * 16 + 4 + i) * 32);
            }

#pragma unroll
            for (int i = 0; i < 4; i++) MMA_BF16(acc[i], a_hi, bhA[i].x, bhA[i].y);
#pragma unroll
            for (int i = 0; i < 4; i++) MMA_BF16(acc[i], a_hi, blA[i].x, blA[i].y);
#pragma unroll
            for (int i = 0; i < 4; i++) MMA_BF16(acc[i], a_lo, bhA[i].x, bhA[i].y);

            if (kk < 7) {
#pragma unroll
                for (int i = 0; i < 4; i++) {
                    bhA[i] = __ldg(bh_base + ((kk + 1) * 16 + i) * 32);
                    blA[i] = __ldg(bl_base + ((kk + 1) * 16 + i) * 32);
                }
            }

#pragma unroll
            for (int i = 0; i < 4; i++) MMA_BF16(acc[4 + i], a_hi, bhB[i].x, bhB[i].y);
#pragma unroll
            for (int i = 0; i < 4; i++) MMA_BF16(acc[4 + i], a_hi, blB[i].x, blB[i].y);
#pragma unroll
            for (int i = 0; i < 4; i++) MMA_BF16(acc[4 + i], a_lo, bhB[i].x, bhB[i].y);
        }

#pragma unroll
        for (int nn = 0; nn < 8; nn++) {
            int col = (half * 8 + nn) * 8 + 2 * tig;
            float2 bb = *reinterpret_cast<const float2*>(bias + col);
            if (is_out) {
                if (r_lo < NN) {
                    float2 hv = *reinterpret_cast<const float2*>(g_h + (size_t)r_lo * DD + col);
                    float2 o;
                    o.x = hv.x + fmaxf(acc[nn][0] + bb.x, 0.f);
                    o.y = hv.y + fmaxf(acc[nn][1] + bb.y, 0.f);
                    *reinterpret_cast<float2*>(dout + (size_t)r_lo * DD + col) = o;
                }
                if (r_hi < NN) {
                    float2 hv = *reinterpret_cast<const float2*>(g_h + (size_t)r_hi * DD + col);
                    float2 o;
                    o.x = hv.x + fmaxf(acc[nn][2] + bb.x, 0.f);
                    o.y = hv.y + fmaxf(acc[nn][3] + bb.y, 0.f);
                    *reinterpret_cast<float2*>(dout + (size_t)r_hi * DD + col) = o;
                }
            } else {
                int cidx = (half * 8 + nn) * 4 + tig;   // col/2
                if (r_lo < NN)
                    oph[(size_t)r_lo * 64 + cidx] = pack_h2(acc[nn][0] + bb.x, acc[nn][1] + bb.y);
                if (r_hi < NN)
                    oph[(size_t)r_hi * 64 + cidx] = pack_h2(acc[nn][2] + bb.x, acc[nn][3] + bb.y);
            }
        }
    }
}

// ---------------------------------------------------------------------------
// Edge kernel: one warp per edge, fp16 gathers (half traffic vs fp32).
// lane l covers dims 4l..4l+3 (uint2 = 4 halves); head = l>>2.
// Scores and scatter accumulation remain fp32.
// ---------------------------------------------------------------------------
__global__ void edge_kernel(const int* __restrict__ src, const int* __restrict__ dst) {
    int warp = (blockIdx.x * blockDim.x + threadIdx.x) >> 5;
    int lane = threadIdx.x & 31;
    if (warp >= EE) return;

    int s = __ldg(src + warp);
    int d = __ldg(dst + warp);

    uint2 kq = __ldg(reinterpret_cast<const uint2*>(g_Kh + (size_t)s * 64) + lane);
    uint2 qq = __ldg(reinterpret_cast<const uint2*>(g_Qh + (size_t)d * 64) + lane);
    uint2 vq = __ldg(reinterpret_cast<const uint2*>(g_Vh + (size_t)s * 64) + lane);

    float2 k0 = unpack_h2(kq.x), k1 = unpack_h2(kq.y);
    float2 q0 = unpack_h2(qq.x), q1 = unpack_h2(qq.y);
    float2 v0 = unpack_h2(vq.x), v1 = unpack_h2(vq.y);

    float p = k0.x * q0.x + k0.y * q0.y + k1.x * q1.x + k1.y * q1.y;
    p += __shfl_xor_sync(0xffffffffu, p, 1);
    p += __shfl_xor_sync(0xffffffffu, p, 2);   // sum over 4 lanes of this head

    float sc = __expf(fminf(fmaxf(p * 0.25f, -5.f), 5.f));

    float4* wptr = reinterpret_cast<float4*>(g_wV + (size_t)d * DD) + lane;
    asm volatile("red.global.add.v4.f32 [%0], {%1, %2, %3, %4};"
                 :: "l"(wptr), "f"(v0.x * sc), "f"(v0.y * sc),
                    "f"(v1.x * sc), "f"(v1.y * sc)
                 : "memory");
    if ((lane & 3) == 0)
        atomicAdd(g_z + (size_t)d * HH + (lane >> 2), sc);
}

// ---------------------------------------------------------------------------
// Norm kernel: attn normalize + LN1 -> g_h, LN2 -> bf16 split (g_thi/g_tlo)
// ---------------------------------------------------------------------------
__global__ void norm_kernel(const float* __restrict__ x,
                            const float* __restrict__ gamma1, const float* __restrict__ beta1,
                            const float* __restrict__ gamma2, const float* __restrict__ beta2) {
    int node = (blockIdx.x * blockDim.x + threadIdx.x) >> 5;
    int lane = threadIdx.x & 31;
    if (node >= NN) return;

    float4 xv = reinterpret_cast<const float4*>(x + (size_t)node * DD)[lane];
    float4 wv = reinterpret_cast<const float4*>(g_wV + (size_t)node * DD)[lane];
    float rz = 1.f / (g_z[(size_t)node * HH + (lane >> 2)] + 1e-3f);

    float4 y;
    y.x = xv.x + wv.x * rz;
    y.y = xv.y + wv.y * rz;
    y.z = xv.z + wv.z * rz;
    y.w = xv.w + wv.w * rz;

    float s  = y.x + y.y + y.z + y.w;
    float sq = y.x * y.x + y.y * y.y + y.z * y.z + y.w * y.w;
#pragma unroll
    for (int o = 16; o > 0; o >>= 1) {
        s  += __shfl_xor_sync(0xffffffffu, s,  o);
        sq += __shfl_xor_sync(0xffffffffu, sq, o);
    }
    float mu  = s * (1.f / DD);
    float var = sq * (1.f / DD) - mu * mu;
    float inv = rsqrtf(var + 1e-5f);

    float4 g1 = reinterpret_cast<const float4*>(gamma1)[lane];
    float4 b1 = reinterpret_cast<const float4*>(beta1)[lane];
    float4 h;
    h.x = (y.x - mu) * inv * g1.x + b1.x;
    h.y = (y.y - mu) * inv * g1.y + b1.y;
    h.z = (y.z - mu) * inv * g1.z + b1.z;
    h.w = (y.w - mu) * inv * g1.w + b1.w;
    reinterpret_cast<float4*>(g_h + (size_t)node * DD)[lane] = h;

    float s2  = h.x + h.y + h.z + h.w;
    float sq2 = h.x * h.x + h.y * h.y + h.z * h.z + h.w * h.w;
#pragma unroll
    for (int o = 16; o > 0; o >>= 1) {
        s2  += __shfl_xor_sync(0xffffffffu, s2,  o);
        sq2 += __shfl_xor_sync(0xffffffffu, sq2, o);
    }
    float mu2  = s2 * (1.f / DD);
    float var2 = sq2 * (1.f / DD) - mu2 * mu2;
    float inv2 = rsqrtf(var2 + 1e-5f);

    float4 g2 = reinterpret_cast<const float4*>(gamma2)[lane];
    float4 b2 = reinterpret_cast<const float4*>(beta2)[lane];
    float4 tt;
    tt.x = (h.x - mu2) * inv2 * g2.x + b2.x;
    tt.y = (h.y - mu2) * inv2 * g2.y + b2.y;
    tt.z = (h.z - mu2) * inv2 * g2.z + b2.z;
    tt.w = (h.w - mu2) * inv2 * g2.w + b2.w;

    __nv_bfloat162 h01 = __floats2bfloat162_rn(tt.x, tt.y);
    __nv_bfloat162 h23 = __floats2bfloat162_rn(tt.z, tt.w);
    float l0 = tt.x - __bfloat162float(h01.x);
    float l1 = tt.y - __bfloat162float(h01.y);
    float l2 = tt.z - __bfloat162float(h23.x);
    float l3 = tt.w - __bfloat162float(h23.y);
    int base = node * 64 + lane * 2;
    g_thi[base]     = *reinterpret_cast<unsigned int*>(&h01);
    g_thi[base + 1] = *reinterpret_cast<unsigned int*>(&h23);
    g_tlo[base]     = pack_bf(l0, l1);
    g_tlo[base + 1] = pack_bf(l2, l3);
}

// ---------------------------------------------------------------------------
extern "C" void kernel_launch(void* const* d_in, const int* in_sizes, int n_in,
                              void* d_out, int out_size) {
    const float* x      = (const float*)d_in[0];
    const int*   src    = (const int*)  d_in[1];
    const int*   dst    = (const int*)  d_in[2];
    const float* Wq     = (const float*)d_in[3];
    const float* bq     = (const float*)d_in[4];
    const float* Wk     = (const float*)d_in[5];
    const float* bk     = (const float*)d_in[6];
    const float* Wv     = (const float*)d_in[7];
    const float* bv     = (const float*)d_in[8];
    const float* Wo     = (const float*)d_in[9];
    const float* bo     = (const float*)d_in[10];
    const float* gamma1 = (const float*)d_in[11];
    const float* beta1  = (const float*)d_in[12];
    const float* gamma2 = (const float*)d_in[13];
    const float* beta2  = (const float*)d_in[14];
    float* out = (float*)d_out;

    const int MMA_SMEM = 2 * 128 * 272;  // 69632 B
    cudaFuncSetAttribute(mma_gemm, cudaFuncAttributeMaxDynamicSharedMemorySize, MMA_SMEM);

    // zero accumulators
    zero_kernel<<<(NN * DD / 4 + 255) / 256, 256>>>();

    // bf16 splits + W fragment bake
    convert_x<<<(NN * 64 + 255) / 256, 256>>>(x);
    convert_w<<<dim3(16, 4), 256>>>(Wq, Wk, Wv, Wo);

    // QKV projections (mma.sync bf16x3) -> fp16-packed Q/K/V
    dim3 qkv_grid((NN + 127) / 128, 3);
    mma_gemm<<<qkv_grid, 256, MMA_SMEM>>>(0, 0, bq, bk, bv, nullptr, 0);

    // edge scores + scatter (fp16 gathers, fp32 atomics)
    edge_kernel<<<EE / 8, 256>>>(src, dst);

    // attn normalize + LN1 + LN2(+split)
    norm_kernel<<<(NN + 7) / 8, 256>>>(x, gamma1, beta1, gamma2, beta2);

    // output projection + relu + residual
    mma_gemm<<<dim3((NN + 127) / 128, 1), 256, MMA_SMEM>>>(1, 3, bo, bo, bo, out, 1);
}

// round 14
// speedup vs baseline: 1.6041x; 1.0135x over previous
#include <cuda_runtime.h>
#include <cuda_bf16.h>
#include <cuda_fp16.h>
#include <math.h>
#include <stdint.h>

#define NN 50000
#define EE 800000
#define DD 128
#define HH 8
#define CNT_PAD 53248   // 1024 threads * 52 ints

// ---------------- scratch (static device arrays, no allocation) -------------
// Q/K/V stored as fp16 (half2-packed): row = 64 uints = 128 halves
__device__ unsigned int g_Qh[NN * 64];
__device__ unsigned int g_Kh[NN * 64];
__device__ unsigned int g_Vh[NN * 64];
__device__ float g_h[NN * DD];
// bf16 hi/lo splits of activations, packed bf16x2 (pair p = cols 2p, 2p+1)
__device__ unsigned int g_xhi[NN * 64];
__device__ unsigned int g_xlo[NN * 64];
__device__ unsigned int g_thi[NN * 64];
__device__ unsigned int g_tlo[NN * 64];
// W pre-baked into m16n8k16 B-fragment layout: [matrix][(kk*16+nn)*32 + lane]
__device__ uint2 g_wfh[4][4096];
__device__ uint2 g_wfl[4][4096];
// CSR by destination
__device__ __align__(16) int g_cnt[CNT_PAD];
__device__ int g_rowptr[NN + 1];
__device__ int g_off[NN];
__device__ int g_esrc[EE];

// ---------------- helpers ---------------------------------------------------
__device__ __forceinline__ unsigned int smem_u32(const void* p) {
    unsigned int a;
    asm("{ .reg .u64 t; cvta.to.shared.u64 t, %1; cvt.u32.u64 %0, t; }" : "=r"(a) : "l"(p));
    return a;
}

__device__ __forceinline__ unsigned int pack_bf(float a, float b) {
    __nv_bfloat162 t = __floats2bfloat162_rn(a, b);
    return *reinterpret_cast<unsigned int*>(&t);
}

__device__ __forceinline__ unsigned int pack_h2(float a, float b) {
    __half2 t = __floats2half2_rn(a, b);
    return *reinterpret_cast<unsigned int*>(&t);
}

__device__ __forceinline__ float2 unpack_h2(unsigned int u) {
    return __half22float2(*reinterpret_cast<__half2*>(&u));
}

#define MMA_BF16(c, a, b0v, b1v)                                               \
    asm volatile("mma.sync.aligned.m16n8k16.row.col.f32.bf16.bf16.f32 "        \
                 "{%0,%1,%2,%3}, {%4,%5,%6,%7}, {%8,%9}, {%0,%1,%2,%3};"       \
                 : "+f"((c)[0]), "+f"((c)[1]), "+f"((c)[2]), "+f"((c)[3])      \
                 : "r"((a)[0]), "r"((a)[1]), "r"((a)[2]), "r"((a)[3]),         \
                   "r"(b0v), "r"(b1v))

#define LDMATRIX_X4(r, addr)                                                   \
    asm volatile("ldmatrix.sync.aligned.m8n8.x4.shared.b16 {%0,%1,%2,%3}, [%4];" \
                 : "=r"((r)[0]), "=r"((r)[1]), "=r"((r)[2]), "=r"((r)[3])      \
                 : "r"(addr))

// ---------------------------------------------------------------------------
// Convert x -> bf16 hi/lo pairs; also zero the CSR histogram counters.
// ---------------------------------------------------------------------------
__global__ void convert_x(const float* __restrict__ x) {
    int i = blockIdx.x * 256 + threadIdx.x;
    if (i < CNT_PAD) g_cnt[i] = 0;
    if (i >= NN * 64) return;
    float2 v = reinterpret_cast<const float2*>(x)[i];
    __nv_bfloat162 hp = __floats2bfloat162_rn(v.x, v.y);
    float l0 = v.x - __bfloat162float(hp.x);
    float l1 = v.y - __bfloat162float(hp.y);
    g_xhi[i] = *reinterpret_cast<unsigned int*>(&hp);
    g_xlo[i] = pack_bf(l0, l1);
}

// ---------------------------------------------------------------------------
// CSR build: histogram (x4) -> single-block scan (int4) -> scatter (x4)
// ---------------------------------------------------------------------------
__global__ void hist_kernel(const int* __restrict__ dst) {
    int i = blockIdx.x * 256 + threadIdx.x;
    if (i < EE / 4) {
        int4 d = reinterpret_cast<const int4*>(dst)[i];
        atomicAdd(&g_cnt[d.x], 1);
        atomicAdd(&g_cnt[d.y], 1);
        atomicAdd(&g_cnt[d.z], 1);
        atomicAdd(&g_cnt[d.w], 1);
    }
}

__global__ void scan_kernel() {
    __shared__ int ssum[1024];
    const int CH4 = 13;               // 13 int4 = 52 ints per thread
    int t = threadIdx.x;
    int base4 = t * CH4;

    int4 vals[CH4];
    int local = 0;
#pragma unroll
    for (int i = 0; i < CH4; i++) {
        vals[i] = reinterpret_cast<const int4*>(g_cnt)[base4 + i];
        local += vals[i].x + vals[i].y + vals[i].z + vals[i].w;
    }
    ssum[t] = local;
    __syncthreads();
    for (int o = 1; o < 1024; o <<= 1) {
        int u = (t >= o) ? ssum[t - o] : 0;
        __syncthreads();
        ssum[t] += u;
        __syncthreads();
    }
    int run = ssum[t] - local;        // exclusive prefix
    int base = t * 52;
#pragma unroll
    for (int i = 0; i < CH4; i++) {
        int idx = base + i * 4;
        int4 v = vals[i];
        if (idx     < NN) { g_rowptr[idx]     = run; g_off[idx]     = run; } run += v.x;
        if (idx + 1 < NN) { g_rowptr[idx + 1] = run; g_off[idx + 1] = run; } run += v.y;
        if (idx + 2 < NN) { g_rowptr[idx + 2] = run; g_off[idx + 2] = run; } run += v.z;
        if (idx + 3 < NN) { g_rowptr[idx + 3] = run; g_off[idx + 3] = run; } run += v.w;
    }
    if (t == 1023) g_rowptr[NN] = run;
}

__global__ void scatter_kernel(const int* __restrict__ src, const int* __restrict__ dst) {
    int i = blockIdx.x * 256 + threadIdx.x;
    if (i < EE / 4) {
        int4 d = reinterpret_cast<const int4*>(dst)[i];
        int4 s = reinterpret_cast<const int4*>(src)[i];
        int p0 = atomicAdd(&g_off[d.x], 1); g_esrc[p0] = s.x;
        int p1 = atomicAdd(&g_off[d.y], 1); g_esrc[p1] = s.y;
        int p2 = atomicAdd(&g_off[d.z], 1); g_esrc[p2] = s.z;
        int p3 = atomicAdd(&g_off[d.w], 1); g_esrc[p3] = s.w;
    }
}

// ---------------------------------------------------------------------------
// Bake W (4 matrices) into mma.sync B-fragment layout (hi + lo splits).
// ---------------------------------------------------------------------------
__global__ void convert_w(const float* __restrict__ Wq, const float* __restrict__ Wk,
                          const float* __restrict__ Wv, const float* __restrict__ Wo) {
    int m = blockIdx.y;
    const float* W = (m == 0) ? Wq : (m == 1) ? Wk : (m == 2) ? Wv : Wo;
    int i = blockIdx.x * 256 + threadIdx.x;
    if (i >= 4096) return;
    int lane = i & 31, nn = (i >> 5) & 15, kk = i >> 9;
    int g = lane >> 2, tig = lane & 3;
    int k0 = kk * 16 + 2 * tig;
    int col = nn * 8 + g;

    float w00 = W[(k0)     * 128 + col];
    float w01 = W[(k0 + 1) * 128 + col];
    float w10 = W[(k0 + 8) * 128 + col];
    float w11 = W[(k0 + 9) * 128 + col];

    __nv_bfloat16 h00 = __float2bfloat16_rn(w00);
    __nv_bfloat16 h01 = __float2bfloat16_rn(w01);
    __nv_bfloat16 h10 = __float2bfloat16_rn(w10);
    __nv_bfloat16 h11 = __float2bfloat16_rn(w11);

    g_wfh[m][i] = make_uint2(pack_bf(w00, w01), pack_bf(w10, w11));
    g_wfl[m][i] = make_uint2(
        pack_bf(w00 - __bfloat162float(h00), w01 - __bfloat162float(h01)),
        pack_bf(w10 - __bfloat162float(h10), w11 - __bfloat162float(h11)));
}

// ---------------------------------------------------------------------------
// mma.sync GEMM: D[128 rows, 128 cols] = A @ W, bf16x3 split, fp32 accum.
// Warp tile = 32 rows x 64 cols (warp = wr*2+wc: wr=row group, wc=col half)
// so each warp loads B fragments for only 64 cols (halves B L1 traffic).
// Processed as two 32x32 col-halves (acc = 32 regs); term-major MMA order
// with distance-8 accumulator chains; rolling B prefetch across kk.
// qkv mode (is_out=0): epilogue packs D+bias to fp16 half2 -> g_Qh/g_Kh/g_Vh
// out mode (is_out=1): out = g_h + relu(D + bo) fp32
// ---------------------------------------------------------------------------
__global__ void __launch_bounds__(256, 3)
mma_gemm(int a_is_t, int w_base, const float* __restrict__ b0,
         const float* __restrict__ b1, const float* __restrict__ b2,
         float* __restrict__ dout, int is_out) {
    extern __shared__ char smem[];
    const int A_STRIDE_B = 272;
    const int OFF_LO = 128 * A_STRIDE_B;
    int t = threadIdx.x, warp = t >> 5, lane = t & 31;
    int sel = blockIdx.y;
    int row0 = blockIdx.x * 128;

    const unsigned int* __restrict__ Ahi = a_is_t ? g_thi : g_xhi;
    const unsigned int* __restrict__ Alo = a_is_t ? g_tlo : g_xlo;
    const uint2* __restrict__ wfh = g_wfh[w_base + sel];
    const uint2* __restrict__ wfl = g_wfl[w_base + sel];
    const float* bias = is_out ? b0 : (sel == 0 ? b0 : sel == 1 ? b1 : b2);
    unsigned int* oph = (sel == 0) ? g_Qh : (sel == 1) ? g_Kh : g_Vh;

    for (int i = t; i < 8192; i += 256) {
        int row = i >> 6, p = i & 63;
        int grow = row0 + row;
        unsigned int vh = 0, vl = 0;
        if (grow < NN) { vh = Ahi[grow * 64 + p]; vl = Alo[grow * 64 + p]; }
        int off = row * A_STRIDE_B + p * 4;
        *reinterpret_cast<unsigned int*>(smem + off)          = vh;
        *reinterpret_cast<unsigned int*>(smem + OFF_LO + off) = vl;
    }
    __syncthreads();

    int wr = warp >> 1;        // 0..3: rows wr*32 .. +31
    int wc = warp & 1;         // 0..1: cols wc*64 .. +63
    int rowsel = (lane & 7) | (((lane >> 3) & 1) << 3);
    int colblk = lane >> 4;
    unsigned int sb = smem_u32(smem);
    unsigned int a_addr0 = sb + (wr * 32 + rowsel) * A_STRIDE_B + colblk * 16;
    unsigned int a_addr1 = a_addr0 + 16 * A_STRIDE_B;

    int g = lane >> 2, tig = lane & 3;

#pragma unroll 1
    for (int h2 = 0; h2 < 2; h2++) {
        // fragment base for this 32-col group: nng = wc*8 + h2*4 + i
        const uint2* bh_base = wfh + (wc * 8 + h2 * 4) * 32 + lane;
        const uint2* bl_base = wfl + (wc * 8 + h2 * 4) * 32 + lane;

        float acc0[4][4], acc1[4][4];
#pragma unroll
        for (int i = 0; i < 4; i++)
#pragma unroll
            for (int c = 0; c < 4; c++) { acc0[i][c] = 0.f; acc1[i][c] = 0.f; }

        uint2 bhA[4], blA[4];
#pragma unroll
        for (int i = 0; i < 4; i++) {
            bhA[i] = __ldg(bh_base + i * 32);
            blA[i] = __ldg(bl_base + i * 32);
        }

#pragma unroll 1
        for (int kk = 0; kk < 8; kk++) {
            unsigned int a0[4], a1[4];
            LDMATRIX_X4(a0, a_addr0 + kk * 32);
            LDMATRIX_X4(a1, a_addr1 + kk * 32);

            uint2 bhN[4], blN[4];
            if (kk < 7) {
#pragma unroll
                for (int i = 0; i < 4; i++) {
                    bhN[i] = __ldg(bh_base + ((kk + 1) * 16) * 32 + i * 32);
                    blN[i] = __ldg(bl_base + ((kk + 1) * 16) * 32 + i * 32);
                }
            }

            // a_hi terms: hi*bh (both tiles), hi*bl (both tiles)
#pragma unroll
            for (int i = 0; i < 4; i++) MMA_BF16(acc0[i], a0, bhA[i].x, bhA[i].y);
#pragma unroll
            for (int i = 0; i < 4; i++) MMA_BF16(acc1[i], a1, bhA[i].x, bhA[i].y);
#pragma unroll
            for (int i = 0; i < 4; i++) MMA_BF16(acc0[i], a0, blA[i].x, blA[i].y);
#pragma unroll
            for (int i = 0; i < 4; i++) MMA_BF16(acc1[i], a1, blA[i].x, blA[i].y);

            // a_lo term: lo*bh (reload a regs with lo fragments)
            LDMATRIX_X4(a0, a_addr0 + OFF_LO + kk * 32);
            LDMATRIX_X4(a1, a_addr1 + OFF_LO + kk * 32);
#pragma unroll
            for (int i = 0; i < 4; i++) MMA_BF16(acc0[i], a0, bhA[i].x, bhA[i].y);
#pragma unroll
            for (int i = 0; i < 4; i++) MMA_BF16(acc1[i], a1, bhA[i].x, bhA[i].y);

#pragma unroll
            for (int i = 0; i < 4; i++) { bhA[i] = bhN[i]; blA[i] = blN[i]; }
        }

        // epilogue: tile tt rows = row0 + wr*32 + tt*16 + g (+8)
#pragma unroll
        for (int tt = 0; tt < 2; tt++) {
            int r_lo = row0 + wr * 32 + tt * 16 + g;
            int r_hi = r_lo + 8;
#pragma unroll
            for (int i = 0; i < 4; i++) {
                float (*ac)[4] = tt ? acc1 : acc0;
                int nng = wc * 8 + h2 * 4 + i;
                int col = nng * 8 + 2 * tig;
                float2 bb = *reinterpret_cast<const float2*>(bias + col);
                if (is_out) {
                    if (r_lo < NN) {
                        float2 hv = *reinterpret_cast<const float2*>(g_h + (size_t)r_lo * DD + col);
                        float2 o;
                        o.x = hv.x + fmaxf(ac[i][0] + bb.x, 0.f);
                        o.y = hv.y + fmaxf(ac[i][1] + bb.y, 0.f);
                        *reinterpret_cast<float2*>(dout + (size_t)r_lo * DD + col) = o;
                    }
                    if (r_hi < NN) {
                        float2 hv = *reinterpret_cast<const float2*>(g_h + (size_t)r_hi * DD + col);
                        float2 o;
                        o.x = hv.x + fmaxf(ac[i][2] + bb.x, 0.f);
                        o.y = hv.y + fmaxf(ac[i][3] + bb.y, 0.f);
                        *reinterpret_cast<float2*>(dout + (size_t)r_hi * DD + col) = o;
                    }
                } else {
                    int cidx = nng * 4 + tig;   // col/2
                    if (r_lo < NN)
                        oph[(size_t)r_lo * 64 + cidx] = pack_h2(ac[i][0] + bb.x, ac[i][1] + bb.y);
                    if (r_hi < NN)
                        oph[(size_t)r_hi * 64 + cidx] = pack_h2(ac[i][2] + bb.x, ac[i][3] + bb.y);
                }
            }
        }
    }
}

// ---------------------------------------------------------------------------
// Fused edge + norm kernel: one warp per destination node (CSR, no atomics).
// fp16 gathers (uint2 = 4 halves per lane); Q loaded once per node; wV and z
// accumulate in registers. Then normalize + residual + LN1 -> g_h fp32 +
// LN2 -> bf16 split (g_thi/g_tlo). Unroll-2 (keeps MLP_p1 modest — unroll-4
// regressed via cross-CTA L1tex-queue contention in R12).
// ---------------------------------------------------------------------------
__global__ void __launch_bounds__(256)
edge_norm_kernel(const float* __restrict__ x,
                 const float* __restrict__ gamma1, const float* __restrict__ beta1,
                 const float* __restrict__ gamma2, const float* __restrict__ beta2) {
    int node = (blockIdx.x * blockDim.x + threadIdx.x) >> 5;
    int lane = threadIdx.x & 31;
    if (node >= NN) return;

    uint2 qq = __ldg(reinterpret_cast<const uint2*>(g_Qh + (size_t)node * 64) + lane);
    float2 q0 = unpack_h2(qq.x), q1 = unpack_h2(qq.y);

    int beg = g_rowptr[node];
    int end = g_rowptr[node + 1];

    float4 wacc = make_float4(0.f, 0.f, 0.f, 0.f);
    float zacc = 0.f;

    int i = beg;
    for (; i + 2 <= end; i += 2) {
        int s0 = __ldg(g_esrc + i);
        int s1 = __ldg(g_esrc + i + 1);
        uint2 kq0 = __ldg(reinterpret_cast<const uint2*>(g_Kh + (size_t)s0 * 64) + lane);
        uint2 kq1 = __ldg(reinterpret_cast<const uint2*>(g_Kh + (size_t)s1 * 64) + lane);
        uint2 vq0 = __ldg(reinterpret_cast<const uint2*>(g_Vh + (size_t)s0 * 64) + lane);
        uint2 vq1 = __ldg(reinterpret_cast<const uint2*>(g_Vh + (size_t)s1 * 64) + lane);

        float2 ka = unpack_h2(kq0.x), kb = unpack_h2(kq0.y);
        float2 kc = unpack_h2(kq1.x), kd = unpack_h2(kq1.y);
        float p0 = ka.x * q0.x + ka.y * q0.y + kb.x * q1.x + kb.y * q1.y;
        float p1 = kc.x * q0.x + kc.y * q0.y + kd.x * q1.x + kd.y * q1.y;
        p0 += __shfl_xor_sync(0xffffffffu, p0, 1);
        p1 += __shfl_xor_sync(0xffffffffu, p1, 1);
        p0 += __shfl_xor_sync(0xffffffffu, p0, 2);
        p1 += __shfl_xor_sync(0xffffffffu, p1, 2);

        float sc0 = __expf(fminf(fmaxf(p0 * 0.25f, -5.f), 5.f));
        float sc1 = __expf(fminf(fmaxf(p1 * 0.25f, -5.f), 5.f));

        float2 va = unpack_h2(vq0.x), vb = unpack_h2(vq0.y);
        float2 vc = unpack_h2(vq1.x), vd = unpack_h2(vq1.y);
        wacc.x += va.x * sc0 + vc.x * sc1;
        wacc.y += va.y * sc0 + vc.y * sc1;
        wacc.z += vb.x * sc0 + vd.x * sc1;
        wacc.w += vb.y * sc0 + vd.y * sc1;
        zacc += sc0 + sc1;
    }
    if (i < end) {
        int s = __ldg(g_esrc + i);
        uint2 kq = __ldg(reinterpret_cast<const uint2*>(g_Kh + (size_t)s * 64) + lane);
        uint2 vq = __ldg(reinterpret_cast<const uint2*>(g_Vh + (size_t)s * 64) + lane);
        float2 ka = unpack_h2(kq.x), kb = unpack_h2(kq.y);
        float p = ka.x * q0.x + ka.y * q0.y + kb.x * q1.x + kb.y * q1.y;
        p += __shfl_xor_sync(0xffffffffu, p, 1);
        p += __shfl_xor_sync(0xffffffffu, p, 2);
        float sc = __expf(fminf(fmaxf(p * 0.25f, -5.f), 5.f));
        float2 va = unpack_h2(vq.x), vb = unpack_h2(vq.y);
        wacc.x += va.x * sc; wacc.y += va.y * sc;
        wacc.z += vb.x * sc; wacc.w += vb.y * sc;
        zacc += sc;
    }

    float rz = 1.f / (zacc + 1e-3f);
    float4 xv = reinterpret_cast<const float4*>(x + (size_t)node * DD)[lane];

    float4 y;
    y.x = xv.x + wacc.x * rz;
    y.y = xv.y + wacc.y * rz;
    y.z = xv.z + wacc.z * rz;
    y.w = xv.w + wacc.w * rz;

    // --- LN1 ---
    float s  = y.x + y.y + y.z + y.w;
    float sq = y.x * y.x + y.y * y.y + y.z * y.z + y.w * y.w;
#pragma unroll
    for (int o = 16; o > 0; o >>= 1) {
        s  += __shfl_xor_sync(0xffffffffu, s,  o);
        sq += __shfl_xor_sync(0xffffffffu, sq, o);
    }
    float mu  = s * (1.f / DD);
    float var = sq * (1.f / DD) - mu * mu;
    float inv = rsqrtf(var + 1e-5f);

    float4 g1 = reinterpret_cast<const float4*>(gamma1)[lane];
    float4 b1 = reinterpret_cast<const float4*>(beta1)[lane];
    float4 h;
    h.x = (y.x - mu) * inv * g1.x + b1.x;
    h.y = (y.y - mu) * inv * g1.y + b1.y;
    h.z = (y.z - mu) * inv * g1.z + b1.z;
    h.w = (y.w - mu) * inv * g1.w + b1.w;
    reinterpret_cast<float4*>(g_h + (size_t)node * DD)[lane] = h;

    // --- LN2 ---
    float s2  = h.x + h.y + h.z + h.w;
    float sq2 = h.x * h.x + h.y * h.y + h.z * h.z + h.w * h.w;
#pragma unroll
    for (int o = 16; o > 0; o >>= 1) {
        s2  += __shfl_xor_sync(0xffffffffu, s2,  o);
        sq2 += __shfl_xor_sync(0xffffffffu, sq2, o);
    }
    float mu2  = s2 * (1.f / DD);
    float var2 = sq2 * (1.f / DD) - mu2 * mu2;
    float inv2 = rsqrtf(var2 + 1e-5f);

    float4 g2 = reinterpret_cast<const float4*>(gamma2)[lane];
    float4 b2 = reinterpret_cast<const float4*>(beta2)[lane];
    float4 tt;
    tt.x = (h.x - mu2) * inv2 * g2.x + b2.x;
    tt.y = (h.y - mu2) * inv2 * g2.y + b2.y;
    tt.z = (h.z - mu2) * inv2 * g2.z + b2.z;
    tt.w = (h.w - mu2) * inv2 * g2.w + b2.w;

    __nv_bfloat162 h01 = __floats2bfloat162_rn(tt.x, tt.y);
    __nv_bfloat162 h23 = __floats2bfloat162_rn(tt.z, tt.w);
    float l0 = tt.x - __bfloat162float(h01.x);
    float l1 = tt.y - __bfloat162float(h01.y);
    float l2 = tt.z - __bfloat162float(h23.x);
    float l3 = tt.w - __bfloat162float(h23.y);
    int base = node * 64 + lane * 2;
    g_thi[base]     = *reinterpret_cast<unsigned int*>(&h01);
    g_thi[base + 1] = *reinterpret_cast<unsigned int*>(&h23);
    g_tlo[base]     = pack_bf(l0, l1);
    g_tlo[base + 1] = pack_bf(l2, l3);
}

// ---------------------------------------------------------------------------
extern "C" void kernel_launch(void* const* d_in, const int* in_sizes, int n_in,
                              void* d_out, int out_size) {
    const float* x      = (const float*)d_in[0];
    const int*   src    = (const int*)  d_in[1];
    const int*   dst    = (const int*)  d_in[2];
    const float* Wq     = (const float*)d_in[3];
    const float* bq     = (const float*)d_in[4];
    const float* Wk     = (const float*)d_in[5];
    const float* bk     = (const float*)d_in[6];
    const float* Wv     = (const float*)d_in[7];
    const float* bv     = (const float*)d_in[8];
    const float* Wo     = (const float*)d_in[9];
    const float* bo     = (const float*)d_in[10];
    const float* gamma1 = (const float*)d_in[11];
    const float* beta1  = (const float*)d_in[12];
    const float* gamma2 = (const float*)d_in[13];
    const float* beta2  = (const float*)d_in[14];
    float* out = (float*)d_out;

    const int MMA_SMEM = 2 * 128 * 272;  // 69632 B
    cudaFuncSetAttribute(mma_gemm, cudaFuncAttributeMaxDynamicSharedMemorySize, MMA_SMEM);

    // x split (+ zero CSR counters)
    convert_x<<<(NN * 64 + 255) / 256, 256>>>(x);

    // CSR build
    hist_kernel<<<(EE / 4 + 255) / 256, 256>>>(dst);
    scan_kernel<<<1, 1024>>>();
    scatter_kernel<<<(EE / 4 + 255) / 256, 256>>>(src, dst);

    // W fragment bake
    convert_w<<<dim3(16, 4), 256>>>(Wq, Wk, Wv, Wo);

    // QKV projections (mma.sync bf16x3) -> fp16-packed Q/K/V
    dim3 qkv_grid((NN + 127) / 128, 3);
    mma_gemm<<<qkv_grid, 256, MMA_SMEM>>>(0, 0, bq, bk, bv, nullptr, 0);

    // fused edge scores + aggregate + normalize + LN1 + LN2(+split)
    edge_norm_kernel<<<(NN + 7) / 8, 256>>>(x, gamma1, beta1, gamma2, beta2);

    // output projection + relu + residual
    mma_gemm<<<dim3((NN + 127) / 128, 1), 256, MMA_SMEM>>>(1, 3, bo, bo, bo, out, 1);
}